// round 9
// baseline (speedup 1.0000x reference)
#include <cuda_runtime.h>
#include <math.h>

#define D_DIM 182
#define H_DIM 218
#define W_DIM 182
#define EMBED_DIM 768
#define REGION_MAX 116

#define TPB 256
#define PPB 256                       // points per block
#define NWARP (TPB / 32)              // 8
#define SLOTS_PER_WARP (PPB / NWARP)  // 32

// first PERSIST_PTS output rows are written with evict_last (pinned dirty set ~96MB)
#define PERSIST_PTS 32768

__device__ __forceinline__ unsigned long long pk(float x, float y) {
    return (unsigned long long)__float_as_uint(x) |
           ((unsigned long long)__float_as_uint(y) << 32);
}

// 32-byte stores with L2 eviction hints (sm_103a requires .v4.b64 for hinted st)
__device__ __forceinline__ void st32_last(void* p, float4 a, float4 b) {
    asm volatile("st.global.L2::evict_last.v4.b64 [%0], {%1,%2,%3,%4};"
                 :: "l"(p), "l"(pk(a.x, a.y)), "l"(pk(a.z, a.w)),
                    "l"(pk(b.x, b.y)), "l"(pk(b.z, b.w)) : "memory");
}
__device__ __forceinline__ void st32_first(void* p, float4 a, float4 b) {
    asm volatile("st.global.L2::evict_first.v4.b64 [%0], {%1,%2,%3,%4};"
                 :: "l"(p), "l"(pk(a.x, a.y)), "l"(pk(a.z, a.w)),
                    "l"(pk(b.x, b.y)), "l"(pk(b.z, b.w)) : "memory");
}

__global__ __launch_bounds__(TPB) void fused_kernel(
    const float* __restrict__ centers,
    const float* __restrict__ mri,
    const float* __restrict__ aal,
    const float* __restrict__ aal_data,
    const float* __restrict__ table,
    float* __restrict__ out,
    int total)
{
    __shared__ float sM[12];
    __shared__ int sHist[128];
    __shared__ int sScan[128];
    __shared__ int sSorted[PPB];      // pt | (region << 20)

    const int tid = threadIdx.x;
    if (tid < 128) sHist[tid] = 0;

    if (tid == 0) {
        // invert aal (4x4 Gauss-Jordan, partial pivot), fuse with mri
        float a[4][8];
        #pragma unroll
        for (int i = 0; i < 4; i++)
            #pragma unroll
            for (int j = 0; j < 4; j++) {
                a[i][j] = aal[i * 4 + j];
                a[i][j + 4] = (i == j) ? 1.0f : 0.0f;
            }
        #pragma unroll
        for (int c = 0; c < 4; c++) {
            int p = c;
            float best = fabsf(a[c][c]);
            for (int r = c + 1; r < 4; r++) {
                float v = fabsf(a[r][c]);
                if (v > best) { best = v; p = r; }
            }
            if (p != c)
                for (int j = 0; j < 8; j++) { float t = a[c][j]; a[c][j] = a[p][j]; a[p][j] = t; }
            float inv = 1.0f / a[c][c];
            for (int j = 0; j < 8; j++) a[c][j] *= inv;
            for (int r = 0; r < 4; r++) {
                if (r == c) continue;
                float f = a[r][c];
                for (int j = 0; j < 8; j++) a[r][j] -= f * a[c][j];
            }
        }
        #pragma unroll
        for (int i = 0; i < 3; i++)
            #pragma unroll
            for (int j = 0; j < 4; j++) {
                float s = 0.0f;
                #pragma unroll
                for (int k = 0; k < 4; k++) s += a[i][k + 4] * mri[k * 4 + j];
                sM[i * 4 + j] = s;
            }
    }
    __syncthreads();

    // ---- Phase 1: region id + block-local rank
    const int base = blockIdx.x * PPB;
    const int pt = base + tid;
    const bool active = (pt < total);
    int region = 0, rank = 0;
    if (active) {
        float x0 = centers[pt * 3 + 0];
        float y0 = centers[pt * 3 + 1];
        float z0 = centers[pt * 3 + 2];
        float X = sM[0] * x0 + sM[1] * y0 + sM[2]  * z0 + sM[3];
        float Y = sM[4] * x0 + sM[5] * y0 + sM[6]  * z0 + sM[7];
        float Z = sM[8] * x0 + sM[9] * y0 + sM[10] * z0 + sM[11];
        int xi = (int)rintf(X);   // round-half-even, matches jnp.round
        int yi = (int)rintf(Y);
        int zi = (int)rintf(Z);
        bool inb = (xi >= 0) & (xi < D_DIM) & (yi >= 0) & (yi < H_DIM) &
                   (zi >= 0) & (zi < W_DIM);
        int cx = min(max(xi, 0), D_DIM - 1);
        int cy = min(max(yi, 0), H_DIM - 1);
        int cz = min(max(zi, 0), W_DIM - 1);
        int r = (int)__ldg(&aal_data[((size_t)cx * H_DIM + cy) * W_DIM + cz]);
        region = (inb && r >= 0 && r <= REGION_MAX) ? r : 0;
        rank = atomicAdd(&sHist[region], 1);
    }
    __syncthreads();

    // ---- block-local exclusive scan over 128 bins (warp 0)
    if (tid < 32) {
        int c0 = sHist[tid * 4 + 0];
        int c1 = sHist[tid * 4 + 1];
        int c2 = sHist[tid * 4 + 2];
        int c3 = sHist[tid * 4 + 3];
        int sum = c0 + c1 + c2 + c3;
        int incl = sum;
        #pragma unroll
        for (int off = 1; off < 32; off <<= 1) {
            int n = __shfl_up_sync(0xffffffffu, incl, off);
            if (tid >= off) incl += n;
        }
        int excl = incl - sum;
        sScan[tid * 4 + 0] = excl;
        sScan[tid * 4 + 1] = excl + c0;
        sScan[tid * 4 + 2] = excl + c0 + c1;
        sScan[tid * 4 + 3] = excl + c0 + c1 + c2;
    }
    __syncthreads();

    // ---- counting sort into smem (region-ordered, packed)
    if (active)
        sSorted[sScan[region] + rank] = pt | (region << 20);
    __syncthreads();

    // ---- Phase 2: parallel region-run copy; each lane owns 32B chunks.
    // Row layout per lane: float4 indices {2*lane, 2*lane+1} + 64*j, j=0..2.
    const int warp = tid >> 5;
    const int lane = tid & 31;
    const int blockPts = min(PPB, total - base);
    const int s0 = warp * SLOTS_PER_WARP;
    const int cnt = min(SLOTS_PER_WARP, blockPts - s0);
    if (cnt <= 0) return;

    int e_mine = (lane < cnt) ? sSorted[s0 + lane] : 0;

    int cur = -1;
    float4 a0, b0, a1, b1, a2, b2;

    for (int i = 0; i < cnt; i++) {
        int e = __shfl_sync(0xffffffffu, e_mine, i);
        int rg = e >> 20;
        int p = e & 0xFFFFF;
        if (rg != cur) {
            const float4* __restrict__ src =
                (const float4*)(table + (size_t)rg * EMBED_DIM);
            a0 = src[2 * lane];       b0 = src[2 * lane + 1];
            a1 = src[2 * lane + 64];  b1 = src[2 * lane + 65];
            a2 = src[2 * lane + 128]; b2 = src[2 * lane + 129];
            cur = rg;
        }
        float4* dst = (float4*)(out + (size_t)p * EMBED_DIM);
        if (p < PERSIST_PTS) {
            st32_last(dst + 2 * lane,       a0, b0);
            st32_last(dst + 2 * lane + 64,  a1, b1);
            st32_last(dst + 2 * lane + 128, a2, b2);
        } else {
            st32_first(dst + 2 * lane,       a0, b0);
            st32_first(dst + 2 * lane + 64,  a1, b1);
            st32_first(dst + 2 * lane + 128, a2, b2);
        }
    }
}

extern "C" void kernel_launch(void* const* d_in, const int* in_sizes, int n_in,
                              void* d_out, int out_size) {
    const float* centers = (const float*)d_in[0];
    const float* mri     = (const float*)d_in[1];
    const float* aal     = (const float*)d_in[2];
    const float* atlas   = (const float*)d_in[3];
    const float* table   = (const float*)d_in[4];
    float* out = (float*)d_out;

    int total = in_sizes[0] / 3;
    int blocks = (total + PPB - 1) / PPB;

    fused_kernel<<<blocks, TPB>>>(centers, mri, aal, atlas, table, out, total);
}